// round 15
// baseline (speedup 1.0000x reference)
#include <cuda_runtime.h>
#include <cuda_fp16.h>
#include <math.h>
#include <cstdint>

#define BB 8
#define SS 1024
#define FF 8
#define DD 512
#define HH 8
#define LL 3
#define EE 4
#define TT (BB*SS)
#define HD 64

// ---------------- scratch (device globals; no allocs allowed) ----------------
__device__ float g_h[TT*DD];
__device__ int   g_cnt[LL*EE];
__device__ int   g_etok[EE*TT];
__device__ int   g_slot[2*TT];
__device__ float g_wt[2*TT];
__device__ float g_istats[BB*FF*2];

__device__ __align__(16) __half g_h16[TT*DD];
__device__ __align__(16) __half g_qkv16[TT*3*DD];
__device__ __align__(16) __half g_attn16[TT*DD];
__device__ __align__(16) __half g_tmp16[TT*DD];
__device__ __align__(16) __half g_hid16[(size_t)EE*TT*2*DD];
__device__ __align__(16) __half g_eo16[(size_t)EE*TT*DD];
__device__ __align__(16) __half g_qkvw16[LL*3*DD*DD];
__device__ __align__(16) __half g_ow16[LL*DD*DD];
__device__ __align__(16) __half g_ew116[(size_t)LL*EE*2*DD*DD];
__device__ __align__(16) __half g_ew216[(size_t)LL*EE*2*DD*DD];

__device__ __forceinline__ uint32_t smem_u32(const void* p) {
    uint32_t a;
    asm("{ .reg .u64 t; cvta.to.shared.u64 t, %1; cvt.u32.u64 %0, t; }" : "=r"(a) : "l"(p));
    return a;
}
__device__ __forceinline__ void mma_f16(float* d, const uint32_t* a, const uint32_t* b) {
    asm volatile(
      "mma.sync.aligned.m16n8k16.row.col.f32.f16.f16.f32 "
      "{%0,%1,%2,%3}, {%4,%5,%6,%7}, {%8,%9}, {%0,%1,%2,%3};"
      : "+f"(d[0]), "+f"(d[1]), "+f"(d[2]), "+f"(d[3])
      : "r"(a[0]), "r"(a[1]), "r"(a[2]), "r"(a[3]), "r"(b[0]), "r"(b[1]));
}
__device__ __forceinline__ void ldm_x4(uint32_t* r, uint32_t addr) {
    asm volatile("ldmatrix.sync.aligned.m8n8.x4.shared.b16 {%0,%1,%2,%3}, [%4];"
        : "=r"(r[0]), "=r"(r[1]), "=r"(r[2]), "=r"(r[3]) : "r"(addr));
}
__device__ __forceinline__ void ldm_x4_t(uint32_t* r, uint32_t addr) {
    asm volatile("ldmatrix.sync.aligned.m8n8.x4.trans.shared.b16 {%0,%1,%2,%3}, [%4];"
        : "=r"(r[0]), "=r"(r[1]), "=r"(r[2]), "=r"(r[3]) : "r"(addr));
}
#define CP_ASYNC16(dst, src, sz) \
  asm volatile("cp.async.cg.shared.global [%0], [%1], 16, %2;" :: "r"(dst), "l"(src), "r"(sz) : "memory")
#define CP_COMMIT() asm volatile("cp.async.commit_group;" ::: "memory")
#define CP_WAIT0()  asm volatile("cp.async.wait_group 0;" ::: "memory")
#define CP_WAIT1()  asm volatile("cp.async.wait_group 1;" ::: "memory")

__device__ __forceinline__ uint32_t h2u(__half2 h) { return *(uint32_t*)&h; }

// ---------------- merged fp32 -> fp16 weight convert ----------------
#define N1F4 (LL*3*DD*DD/4)
#define N2F4 (LL*DD*DD/4)
#define N3F4 (LL*EE*2*DD*DD/4)
#define NTOTF4 (N1F4 + N2F4 + 2*N3F4)
__global__ void f2h_all_kernel(const float* __restrict__ s1, __half* __restrict__ d1,
                               const float* __restrict__ s2, __half* __restrict__ d2,
                               const float* __restrict__ s3, __half* __restrict__ d3,
                               const float* __restrict__ s4, __half* __restrict__ d4)
{
    long i = (long)blockIdx.x * 256 + threadIdx.x;
    if (i >= NTOTF4) return;
    const float* src; __half* dst; long j;
    if (i < N1F4)                    { src = s1; dst = d1; j = i; }
    else if (i < N1F4 + N2F4)        { src = s2; dst = d2; j = i - N1F4; }
    else if (i < N1F4 + N2F4 + N3F4) { src = s3; dst = d3; j = i - N1F4 - N2F4; }
    else                             { src = s4; dst = d4; j = i - N1F4 - N2F4 - N3F4; }
    float4 v = ((const float4*)src)[j];
    __half2* op = (__half2*)(dst + 4*j);
    op[0] = __floats2half2_rn(v.x, v.y);
    op[1] = __floats2half2_rn(v.z, v.w);
}

// ========== fp16 mma GEMM (champion): 128x128 tile, 3-stage cp.async ==========
#define GBUF (128*144)
#define GEMM_SMEM (6*GBUF)
template<bool GATHER, bool RELU>
__global__ void __launch_bounds__(256) gemm_h(
    const __half* __restrict__ A, const __half* __restrict__ W,
    const float* __restrict__ bias, __half* __restrict__ C16,
    int M, int N, int Kd, int lda, int ldc,
    long astride, long wstride, int bstride, long cstride,
    const int* __restrict__ gidx, const int* __restrict__ cnts)
{
    extern __shared__ char smem[];
    int e = blockIdx.z;
    A    += (long)e * astride;
    W    += (long)e * wstride;
    bias += (long)e * bstride;
    C16  += (long)e * cstride;
    if (cnts) M = cnts[e];
    int m0 = blockIdx.y * 128;
    if (m0 >= M) return;
    int n0 = blockIdx.x * 128;

    int tid = threadIdx.x, lane = tid & 31, warp = tid >> 5;
    int g = lane >> 2, t = lane & 3;
    int wm = (warp >> 2) * 64, wn = (warp & 3) * 32;

    uint32_t sb = smem_u32(smem);
    int rbase = tid >> 3, c8 = tid & 7;

    const __half* asrc[4]; uint32_t asz[4];
    const __half* bsrc[4];
    uint32_t adst[4], bdst[4];
#pragma unroll
    for (int p = 0; p < 4; p++) {
        int row = rbase + p * 32;
        int mr = m0 + row;
        bool ok = mr < M;
        int ar = 0;
        if (ok) ar = GATHER ? gidx[(long)e * TT + mr] : mr;
        asrc[p] = A + (long)ar * lda + c8 * 8;
        asz[p] = ok ? 16u : 0u;
        bsrc[p] = W + (long)(n0 + row) * Kd + c8 * 8;
        adst[p] = sb + row * 144 + c8 * 16;
        bdst[p] = sb + 3*GBUF + row * 144 + c8 * 16;
    }

    uint32_t qrow  = (lane & 7) + ((lane >> 3) & 1) * 8;
    uint32_t khalf = (lane >> 4) * 16;
    uint32_t offA[4], offB[2];
#pragma unroll
    for (int mf = 0; mf < 4; mf++) offA[mf] = (wm + mf*16 + qrow) * 144 + khalf;
#pragma unroll
    for (int j = 0; j < 2; j++)
        offB[j] = (uint32_t)(wn + j*16 + ((lane >> 4) & 1)*8 + (lane & 7)) * 144
                + ((lane >> 3) & 1) * 16;

    float acc[4][4][4];
#pragma unroll
    for (int a_ = 0; a_ < 4; a_++)
#pragma unroll
        for (int b_ = 0; b_ < 4; b_++)
#pragma unroll
            for (int c_ = 0; c_ < 4; c_++) acc[a_][b_][c_] = 0.f;

    int nkt = Kd / 64;

    #define STAGE(s) do { \
        uint32_t _off = (uint32_t)((s) % 3) * GBUF; \
        int _ko = (s) * 64; \
        _Pragma("unroll") \
        for (int p = 0; p < 4; p++) { \
            CP_ASYNC16(adst[p] + _off, asrc[p] + _ko, asz[p]); \
            CP_ASYNC16(bdst[p] + _off, bsrc[p] + _ko, 16u); \
        } \
        CP_COMMIT(); \
    } while (0)

    STAGE(0);
    STAGE(1);

    for (int kt = 0; kt < nkt; kt++) {
        if (kt + 1 < nkt) CP_WAIT1(); else CP_WAIT0();
        __syncthreads();
        if (kt + 2 < nkt) STAGE(kt + 2);

        uint32_t ab = sb + (uint32_t)(kt % 3) * GBUF;
        uint32_t bb = sb + 3*GBUF + (uint32_t)(kt % 3) * GBUF;
#pragma unroll
        for (int ks = 0; ks < 4; ks++) {
            uint32_t af[4][4], bf[2][4];
#pragma unroll
            for (int mf = 0; mf < 4; mf++) ldm_x4(af[mf], ab + offA[mf] + ks*32);
#pragma unroll
            for (int j = 0; j < 2; j++) ldm_x4(bf[j], bb + offB[j] + ks*32);
#pragma unroll
            for (int mf = 0; mf < 4; mf++)
#pragma unroll
                for (int nf = 0; nf < 4; nf++)
                    mma_f16(acc[mf][nf], af[mf], &bf[nf >> 1][(nf & 1) * 2]);
        }
    }
    #undef STAGE

#pragma unroll
    for (int mf = 0; mf < 4; mf++) {
        int rA = m0 + wm + mf*16 + g;
        int rB = rA + 8;
#pragma unroll
        for (int nf = 0; nf < 4; nf++) {
            int col = n0 + wn + nf*8 + t*2;
            float2 bb2 = *(const float2*)&bias[col];
            float2 v0, v1;
            v0.x = acc[mf][nf][0] + bb2.x; v0.y = acc[mf][nf][1] + bb2.y;
            v1.x = acc[mf][nf][2] + bb2.x; v1.y = acc[mf][nf][3] + bb2.y;
            if (RELU) {
                v0.x = fmaxf(v0.x, 0.f); v0.y = fmaxf(v0.y, 0.f);
                v1.x = fmaxf(v1.x, 0.f); v1.y = fmaxf(v1.y, 0.f);
            }
            if (rA < M) *(__half2*)&C16[(long)rA*ldc + col] = __floats2half2_rn(v0.x, v0.y);
            if (rB < M) *(__half2*)&C16[(long)rB*ldc + col] = __floats2half2_rn(v1.x, v1.y);
        }
    }
}

// ===== attention (layers 0..1): flash fp16 mma, register-resident P =====
#define AQB 0
#define AKB 18432
#define AVB 36864
#define AKVB 9216
#define ATT_SMEM 55296
__global__ void __launch_bounds__(256) attn_h_kernel(const __half* __restrict__ qkv,
                                                     __half* __restrict__ out)
{
    extern __shared__ char smc[];
    uint32_t sb = smem_u32(smc);

    int q0 = blockIdx.x * 128;
    int hh = blockIdx.y;
    int b  = blockIdx.z;
    int tid = threadIdx.x, lane = tid & 31, warp = tid >> 5;
    int g = lane >> 2, t = lane & 3;
    const __half* base  = qkv + (long)b * SS * (3*DD) + hh * HD;
    const __half* kbase = base + DD;
    const __half* vbase = base + 2*DD;

    int srow0 = tid >> 3, sc8 = tid & 7;
    int srow1 = srow0 + 32;
    uint32_t kd0 = sb + AKB + srow0*144 + sc8*16;
    uint32_t kd1 = sb + AKB + srow1*144 + sc8*16;
    uint32_t vd0 = sb + AVB + srow0*144 + sc8*16;
    uint32_t vd1 = sb + AVB + srow1*144 + sc8*16;

    {
        const __half* k0 = kbase + (long)srow0*(3*DD) + sc8*8;
        const __half* k1 = kbase + (long)srow1*(3*DD) + sc8*8;
        const __half* v0 = vbase + (long)srow0*(3*DD) + sc8*8;
        const __half* v1 = vbase + (long)srow1*(3*DD) + sc8*8;
        CP_ASYNC16(kd0, k0, 16u); CP_ASYNC16(kd1, k1, 16u);
        CP_ASYNC16(vd0, v0, 16u); CP_ASYNC16(vd1, v1, 16u);
    }
    CP_COMMIT();

#pragma unroll
    for (int p = 0; p < 4; p++) {
        int idx = tid + p*256;
        int row = idx >> 3, c8 = idx & 7;
        *(uint4*)(smc + AQB + row*144 + c8*16) =
            *(const uint4*)(base + (long)(q0 + row) * (3*DD) + c8*8);
    }

    uint32_t qrow  = (lane & 7) + ((lane >> 3) & 1) * 8;
    uint32_t khalf = (lane >> 4) * 16;
    uint32_t offQ = sb + AQB + (warp*16 + qrow)*144 + khalf;
    uint32_t offK[4], offV[4];
#pragma unroll
    for (int j = 0; j < 4; j++)
        offK[j] = (uint32_t)(j*16 + ((lane >> 4) & 1)*8 + (lane & 7)) * 144
                + ((lane >> 3) & 1) * 16;
    {
        uint32_t kr = ((lane >> 3) & 1)*8 + (lane & 7);
#pragma unroll
        for (int j = 0; j < 4; j++)
            offV[j] = kr*144 + j*32 + ((lane >> 4) & 1)*16;
    }

    int r0 = warp*16 + g;
    float mm0 = -1e30f, mm1 = -1e30f, ll0 = 0.f, ll1 = 0.f;
    float o[8][4];
#pragma unroll
    for (int nf = 0; nf < 8; nf++)
#pragma unroll
        for (int c = 0; c < 4; c++) o[nf][c] = 0.f;

    for (int jc = 0; jc < SS/64; jc++) {
        int buf = jc & 1;
        CP_WAIT0();
        __syncthreads();
        if (jc + 1 < SS/64) {
            uint32_t nb = (uint32_t)(buf ^ 1) * AKVB;
            long goff = (long)(jc + 1) * 64 * (3*DD);
            const __half* k0 = kbase + goff + (long)srow0*(3*DD) + sc8*8;
            const __half* k1 = kbase + goff + (long)srow1*(3*DD) + sc8*8;
            const __half* v0 = vbase + goff + (long)srow0*(3*DD) + sc8*8;
            const __half* v1 = vbase + goff + (long)srow1*(3*DD) + sc8*8;
            CP_ASYNC16(kd0 + nb, k0, 16u); CP_ASYNC16(kd1 + nb, k1, 16u);
            CP_ASYNC16(vd0 + nb, v0, 16u); CP_ASYNC16(vd1 + nb, v1, 16u);
            CP_COMMIT();
        }
        uint32_t kb = sb + AKB + buf * AKVB;
        uint32_t vb = sb + AVB + buf * AKVB;

        float s[8][4];
#pragma unroll
        for (int nf = 0; nf < 8; nf++)
#pragma unroll
            for (int c = 0; c < 4; c++) s[nf][c] = 0.f;
#pragma unroll
        for (int ks = 0; ks < 4; ks++) {
            uint32_t a[4];
            ldm_x4(a, offQ + ks*32);
#pragma unroll
            for (int j = 0; j < 4; j++) {
                uint32_t bfr[4];
                ldm_x4(bfr, kb + offK[j] + ks*32);
                mma_f16(s[2*j],   a, &bfr[0]);
                mma_f16(s[2*j+1], a, &bfr[2]);
            }
        }
        float mx0 = mm0, mx1 = mm1;
#pragma unroll
        for (int nf = 0; nf < 8; nf++) {
            s[nf][0] *= 0.125f; s[nf][1] *= 0.125f;
            s[nf][2] *= 0.125f; s[nf][3] *= 0.125f;
            mx0 = fmaxf(mx0, fmaxf(s[nf][0], s[nf][1]));
            mx1 = fmaxf(mx1, fmaxf(s[nf][2], s[nf][3]));
        }
        mx0 = fmaxf(mx0, __shfl_xor_sync(0xffffffffu, mx0, 1));
        mx0 = fmaxf(mx0, __shfl_xor_sync(0xffffffffu, mx0, 2));
        mx1 = fmaxf(mx1, __shfl_xor_sync(0xffffffffu, mx1, 1));
        mx1 = fmaxf(mx1, __shfl_xor_sync(0xffffffffu, mx1, 2));
        float al0 = __expf(mm0 - mx0), al1 = __expf(mm1 - mx1);
        float sum0 = 0.f, sum1 = 0.f;
#pragma unroll
        for (int nf = 0; nf < 8; nf++) {
            s[nf][0] = __expf(s[nf][0] - mx0);
            s[nf][1] = __expf(s[nf][1] - mx0);
            s[nf][2] = __expf(s[nf][2] - mx1);
            s[nf][3] = __expf(s[nf][3] - mx1);
            sum0 += s[nf][0] + s[nf][1];
            sum1 += s[nf][2] + s[nf][3];
        }
        sum0 += __shfl_xor_sync(0xffffffffu, sum0, 1);
        sum0 += __shfl_xor_sync(0xffffffffu, sum0, 2);
        sum1 += __shfl_xor_sync(0xffffffffu, sum1, 1);
        sum1 += __shfl_xor_sync(0xffffffffu, sum1, 2);
        ll0 = ll0*al0 + sum0; ll1 = ll1*al1 + sum1;
        mm0 = mx0; mm1 = mx1;
#pragma unroll
        for (int nf = 0; nf < 8; nf++) {
            o[nf][0] *= al0; o[nf][1] *= al0;
            o[nf][2] *= al1; o[nf][3] *= al1;
        }
#pragma unroll
        for (int ks = 0; ks < 4; ks++) {
            uint32_t a[4];
            a[0] = h2u(__floats2half2_rn(s[2*ks][0],   s[2*ks][1]));
            a[1] = h2u(__floats2half2_rn(s[2*ks][2],   s[2*ks][3]));
            a[2] = h2u(__floats2half2_rn(s[2*ks+1][0], s[2*ks+1][1]));
            a[3] = h2u(__floats2half2_rn(s[2*ks+1][2], s[2*ks+1][3]));
#pragma unroll
            for (int j = 0; j < 4; j++) {
                uint32_t bfr[4];
                ldm_x4_t(bfr, vb + offV[j] + ks*2304);
                mma_f16(o[2*j],   a, &bfr[0]);
                mma_f16(o[2*j+1], a, &bfr[2]);
            }
        }
    }

    float inv0 = 1.f / ll0, inv1 = 1.f / ll1;
    long tok0 = (long)(b*SS + q0 + r0) * DD + hh*HD;
    long tok1 = tok0 + 8L*DD;
#pragma unroll
    for (int nf = 0; nf < 8; nf++) {
        int col = nf*8 + 2*t;
        *(__half2*)&out[tok0 + col] = __floats2half2_rn(o[nf][0]*inv0, o[nf][1]*inv0);
        *(__half2*)&out[tok1 + col] = __floats2half2_rn(o[nf][2]*inv1, o[nf][3]*inv1);
    }
}

// ======= fused layer-2 tail: one block per batch (8 blocks) =======
// Q GEMM -> 8 head attentions -> O-proj -> add+LN+gate -> 2 expert FFNs -> combine+LN -> head
__global__ void __launch_bounds__(256) tail_kernel(
    const float* __restrict__ h, const __half* __restrict__ h16,
    const __half* __restrict__ qkv,
    const __half* __restrict__ qw, const float* __restrict__ qb,
    const __half* __restrict__ ow, const float* __restrict__ obv,
    const float* __restrict__ g1, const float* __restrict__ beta1,
    const float* __restrict__ gw, const float* __restrict__ gb,
    const __half* __restrict__ ew1, const float* __restrict__ eb1,
    const __half* __restrict__ ew2, const float* __restrict__ eb2,
    const float* __restrict__ g2, const float* __restrict__ beta2,
    const float* __restrict__ hwp, const float* __restrict__ hbp,
    float* __restrict__ out)
{
    __shared__ float hr[512];
    __shared__ float q[512];
    __shared__ float sc[1024];
    __shared__ float attnv[512];
    __shared__ float ln1[512];
    __shared__ float hid[2][1024];
    __shared__ float eo[2][512];
    __shared__ float red[16];
    __shared__ float obuf[4][64];
    __shared__ float glog[4];
    __shared__ int   eidx[2];
    __shared__ float ewt[2];

    int b = blockIdx.x;
    long tok = (long)b*SS + SS - 1;
    int tid = threadIdx.x, lane = tid & 31, warp = tid >> 5;

    for (int i = tid; i < 512; i += 256) hr[i] = h[tok*DD + i];
    const __half2* h2r = (const __half2*)(h16 + tok*DD);
    for (int oi = tid; oi < 512; oi += 256) {
        const __half2* wr = (const __half2*)(qw + (long)oi*DD);
        float acc = 0.f;
        for (int k = 0; k < 256; k++) {
            float2 hf = __half22float2(h2r[k]);
            float2 wf = __half22float2(wr[k]);
            acc += hf.x*wf.x + hf.y*wf.y;
        }
        q[oi] = acc + qb[oi];
    }
    __syncthreads();

    // per-head attention over all 1024 keys
    for (int hh = 0; hh < HH; hh++) {
        const __half* kb = qkv + (long)b*SS*(3*DD) + DD + hh*HD;
        float mymax = -1e30f;
        for (int j = tid; j < SS; j += 256) {
            const __half2* kr = (const __half2*)(kb + (long)j*(3*DD));
            float s = 0.f;
#pragma unroll
            for (int i = 0; i < 32; i++) {
                float2 kf = __half22float2(kr[i]);
                s += q[hh*64 + 2*i]*kf.x + q[hh*64 + 2*i + 1]*kf.y;
            }
            s *= 0.125f;
            sc[j] = s;
            mymax = fmaxf(mymax, s);
        }
#pragma unroll
        for (int o = 16; o; o >>= 1) mymax = fmaxf(mymax, __shfl_xor_sync(0xffffffffu, mymax, o));
        if (!lane) red[warp] = mymax;
        __syncthreads();
        float smax = fmaxf(fmaxf(fmaxf(red[0], red[1]), fmaxf(red[2], red[3])),
                           fmaxf(fmaxf(red[4], red[5]), fmaxf(red[6], red[7])));
        float mysum = 0.f;
        for (int j = tid; j < SS; j += 256) {
            float p = __expf(sc[j] - smax);
            sc[j] = p;
            mysum += p;
        }
#pragma unroll
        for (int o = 16; o; o >>= 1) mysum += __shfl_xor_sync(0xffffffffu, mysum, o);
        __syncthreads();
        if (!lane) red[warp] = mysum;
        __syncthreads();
        float ssum = red[0]+red[1]+red[2]+red[3]+red[4]+red[5]+red[6]+red[7];

        int d = tid & 63, grp = tid >> 6;
        const __half* vb = qkv + (long)b*SS*(3*DD) + 2*DD + hh*HD + d;
        float acc = 0.f;
        for (int j = grp*256; j < grp*256 + 256; j++)
            acc += sc[j] * __half2float(vb[(long)j*(3*DD)]);
        obuf[grp][d] = acc;
        __syncthreads();
        if (tid < 64)
            attnv[hh*64 + tid] = (obuf[0][tid]+obuf[1][tid]+obuf[2][tid]+obuf[3][tid]) / ssum;
        __syncthreads();
    }

    // O-proj + residual add
    for (int oi = tid; oi < 512; oi += 256) {
        const __half2* wr = (const __half2*)(ow + (long)oi*DD);
        float acc = 0.f;
        for (int k = 0; k < 256; k++) {
            float2 wf = __half22float2(wr[k]);
            acc += attnv[2*k]*wf.x + attnv[2*k+1]*wf.y;
        }
        ln1[oi] = hr[oi] + acc + obv[oi];
    }
    __syncthreads();

    // LN1
    {
        float s = 0.f, ssq = 0.f;
        for (int i = tid; i < 512; i += 256) { float v = ln1[i]; s += v; ssq += v*v; }
#pragma unroll
        for (int o = 16; o; o >>= 1) {
            s   += __shfl_xor_sync(0xffffffffu, s, o);
            ssq += __shfl_xor_sync(0xffffffffu, ssq, o);
        }
        if (!lane) { red[warp] = s; red[8+warp] = ssq; }
        __syncthreads();
        if (!tid) {
            float S = red[0]+red[1]+red[2]+red[3]+red[4]+red[5]+red[6]+red[7];
            float Q = red[8]+red[9]+red[10]+red[11]+red[12]+red[13]+red[14]+red[15];
            red[0] = S * (1.f/512.f);
            red[1] = Q * (1.f/512.f);
        }
        __syncthreads();
        float m = red[0];
        float r = rsqrtf(red[1] - m*m + 1e-5f);
        for (int i = tid; i < 512; i += 256)
            ln1[i] = (ln1[i] - m) * r * g1[i] + beta1[i];
        __syncthreads();
    }

    // gating (4 logits via warps 0..3)
    if (warp < 4) {
        float acc = 0.f;
        for (int i = lane; i < 512; i += 32) acc += ln1[i] * gw[warp*DD + i];
#pragma unroll
        for (int o = 16; o; o >>= 1) acc += __shfl_xor_sync(0xffffffffu, acc, o);
        if (!lane) glog[warp] = acc + gb[warp];
    }
    __syncthreads();
    if (!tid) {
        float mx = fmaxf(fmaxf(glog[0], glog[1]), fmaxf(glog[2], glog[3]));
        float p[4], sum = 0.f;
#pragma unroll
        for (int e = 0; e < 4; e++) { p[e] = expf(glog[e]-mx); sum += p[e]; }
#pragma unroll
        for (int e = 0; e < 4; e++) p[e] /= sum;
        int i0 = 0;
#pragma unroll
        for (int e = 1; e < 4; e++) if (p[e] > p[i0]) i0 = e;
        int i1 = (i0 == 0) ? 1 : 0;
#pragma unroll
        for (int e = 0; e < 4; e++) if (e != i0 && p[e] > p[i1]) i1 = e;
        float inv = 1.f / (p[i0] + p[i1]);
        eidx[0] = i0; eidx[1] = i1;
        ewt[0] = p[i0]*inv; ewt[1] = p[i1]*inv;
    }
    __syncthreads();

    // expert FFN layer 1 (relu)
#pragma unroll
    for (int e = 0; e < 2; e++) {
        const __half* w1 = ew1 + (long)eidx[e]*2*DD*DD;
        const float* b1 = eb1 + eidx[e]*2*DD;
        for (int f = tid; f < 1024; f += 256) {
            const __half2* wr = (const __half2*)(w1 + (long)f*DD);
            float acc = 0.f;
            for (int k = 0; k < 256; k++) {
                float2 wf = __half22float2(wr[k]);
                acc += ln1[2*k]*wf.x + ln1[2*k+1]*wf.y;
            }
            hid[e][f] = fmaxf(acc + b1[f], 0.f);
        }
    }
    __syncthreads();
    // expert FFN layer 2
#pragma unroll
    for (int e = 0; e < 2; e++) {
        const __half* w2 = ew2 + (long)eidx[e]*2*DD*DD;
        const float* b2 = eb2 + eidx[e]*DD;
        for (int d = tid; d < 512; d += 256) {
            const __half2* wr = (const __half2*)(w2 + (long)d*2*DD);
            float acc = 0.f;
            for (int k = 0; k < 512; k++) {
                float2 wf = __half22float2(wr[k]);
                acc += hid[e][2*k]*wf.x + hid[e][2*k+1]*wf.y;
            }
            eo[e][d] = acc + b2[d];
        }
    }
    __syncthreads();

    // combine + LN2 (reuse ln1)
    for (int d = tid; d < 512; d += 256)
        ln1[d] = hr[d] /* pre-attn residual? no: residual base is post-LN1 chain */;
    // NOTE: residual base for MoE is the post-attention LN output's input h (i.e. LN1 input),
    // per reference: h = ln(h + moe) where h is the post-attn LN output. Use saved ln-input:
    __syncthreads();
    for (int d = tid; d < 512; d += 256) {
        // reference: h_after_attnLN = ln1's OUTPUT. moe input/residual base = that output.
        float base = (ln1[d] = 0.f, 0.f); (void)base;
    }
    // recompute properly: residual base is LN1 output, which is still... we overwrote? No: ln1 holds LN1 output.
    __syncthreads();
    // Undo the erroneous zeroing above is impossible; instead structure below uses ln1Out saved in attnv (unused now)
    if (false) {}
    // --- the two loops above are logically dead; real combine below uses attnv backup ---
    for (int d = tid; d < 512; d += 256)
        sc[d] = attnv[d]; // dead
    __syncthreads();

    if (!tid) { }
    __syncthreads();

    // real path: we must not have clobbered ln1. (Handled by backup below.)
    out[0] = out[0]; // no-op
}

// ---------------- instance-norm stats (+ zero MoE counters) ----------------
__global__ void istats_kernel(const float* __restrict__ x, float* __restrict__ stats,
                              int* __restrict__ cntAll)
{
    int bf = blockIdx.x;
    int b = bf >> 3, f = bf & 7;
    int tid = threadIdx.x;
    if (bf == 0 && tid < LL*EE) cntAll[tid] = 0;
    float s = 0.f, ss = 0.f;
    for (int i = tid; i < SS; i += 256) {
        float v = x[((long)b*SS + i)*FF + f];
        s += v; ss += v*v;
    }
    __shared__ float red[16];
    int lane = tid & 31, wid = tid >> 5;
#pragma unroll
    for (int o = 16; o; o >>= 1) {
        s  += __shfl_down_sync(0xffffffffu, s, o);
        ss += __shfl_down_sync(0xffffffffu, ss, o);
    }
    if (!lane) { red[wid] = s; red[8+wid] = ss; }
    __syncthreads();
    if (!tid) {
        float S = 0.f, Q = 0.f;
        for (int w = 0; w < 8; w++) { S += red[w]; Q += red[8+w]; }
        float m = S / SS;
        float var = (Q - SS*m*m) / (SS - 1);
        stats[bf*2]   = m;
        stats[bf*2+1] = 1.f / (sqrtf(var) + 1e-5f);
    }
}

// ---------------- embed (fp32 residual + fp16 shadow) ----------------
__global__ void embed_kernel(const float* __restrict__ x, const float* __restrict__ Wp,
                             const float* __restrict__ bp, const float* __restrict__ femb,
                             const int* __restrict__ fidx, const float* __restrict__ stats,
                             float* __restrict__ h, __half* __restrict__ h16)
{
    int token = blockIdx.x;
    int b = token >> 10, s = token & 1023;
    int tid = threadIdx.x;
    __shared__ float xn[8];
    if (tid < 8) {
        float m = stats[(b*8+tid)*2], inv = stats[(b*8+tid)*2+1];
        xn[tid] = (x[(long)token*FF + tid] - m) * inv;
    }
    __syncthreads();
    int fi = *fidx;
    int d0 = tid * 4;
    float4 acc = *(const float4*)&bp[d0];
    float* ap = &acc.x;
#pragma unroll
    for (int f = 0; f < 8; f++) {
        float xv = xn[f];
        ap[0] += xv * Wp[(d0+0)*8+f];
        ap[1] += xv * Wp[(d0+1)*8+f];
        ap[2] += xv * Wp[(d0+2)*8+f];
        ap[3] += xv * Wp[(d0+3)*8+f];
    }
    const float c = -0.0179889460f;
#pragma unroll
    for (int j = 0; j < 4; j++) {
        int d = d0 + j;
        int i = d >> 1;
        float ang = (float)s * expf((float)(2*i) * c);
        float pe = (d & 1) ? cosf(ang) : sinf(ang);
        ap[j] += femb[fi*DD + d] + pe;
    }
    *(float4*)&h[(long)token*DD + d0] = acc;
    __half2* hp = (__half2*)&h16[(long)token*DD + d0];
    hp[0] = __floats2half2_rn(acc.x, acc.y);
    hp[1] = __floats2half2_rn(acc.z, acc.w);
}

// ---------------- add + layernorm + fused gating ----------------
__global__ void add_ln_gate_kernel(const float* __restrict__ base, const __half* __restrict__ add,
                                   const float* __restrict__ g, const float* __restrict__ bet,
                                   const float* __restrict__ gw, const float* __restrict__ gb,
                                   float* __restrict__ out, __half* __restrict__ out16,
                                   int* __restrict__ cnt, int* __restrict__ etok,
                                   int* __restrict__ slot, float* __restrict__ wt)
{
    long tk = blockIdx.x;
    int tid = threadIdx.x;
    float4 xb = *(const float4*)&base[tk*DD + tid*4];
    uint2 au = *(const uint2*)&add[tk*DD + tid*4];
    float2 aa = __half22float2(*(__half2*)&au.x);
    float2 ab = __half22float2(*(__half2*)&au.y);
    float v0=xb.x+aa.x, v1=xb.y+aa.y, v2=xb.z+ab.x, v3=xb.w+ab.y;
    float s = v0+v1+v2+v3, ss = v0*v0+v1*v1+v2*v2+v3*v3;
    __shared__ float red[16];
    __shared__ float gred[4][4];
    int lane = tid & 31, wid = tid >> 5;
#pragma unroll
    for (int o = 16; o; o >>= 1) {
        s  += __shfl_down_sync(0xffffffffu, s, o);
        ss += __shfl_down_sync(0xffffffffu, ss, o);
    }
    if (!lane) { red[wid] = s; red[8+wid] = ss; }
    __syncthreads();
    if (!tid) {
        float S = red[0]+red[1]+red[2]+red[3];
        float Q = red[8]+red[9]+red[10]+red[11];
        red[0] = S * (1.f/DD);
        red[1] = Q * (1.f/DD);
    }
    __syncthreads();
    float m = red[0];
    float r = rsqrtf(red[1] - m*m + 1e-5f);
    float4 gv = *(const float4*)&g[tid*4];
    float4 bv = *(const float4*)&bet[tid*4];
    float4 o4;
    o4.x = (v0-m)*r*gv.x + bv.x;
    o4.y = (v1-m)*r*gv.y + bv.y;
    o4.z = (v2-m)*r*gv.z + bv.z;
    o4.w = (v3-m)*r*gv.w + bv.w;
    *(float4*)&out[tk*DD + tid*4] = o4;
    __half2* hp = (__half2*)&out16[tk*DD + tid*4];
    hp[0] = __floats2half2_rn(o4.x, o4.y);
    hp[1] = __floats2half2_rn(o4.z, o4.w);

    float p[4];
#pragma unroll
    for (int e = 0; e < 4; e++) {
        float4 wv = *(const float4*)&gw[e*DD + tid*4];
        p[e] = o4.x*wv.x + o4.y*wv.y + o4.z*wv.z + o4.w*wv.w;
    }
#pragma unroll
    for (int e = 0; e < 4; e++)
#pragma unroll
        for (int o = 16; o; o >>= 1)
            p[e] += __shfl_down_sync(0xffffffffu, p[e], o);
    if (!lane) {
        gred[wid][0] = p[0]; gred[wid][1] = p[1];
        gred[wid][2] = p[2]; gred[wid][3] = p[3];
    }
    __syncthreads();
    if (!tid) {
        float lg[4], pr[4];
        float mx = -1e30f;
#pragma unroll
        for (int e = 0; e < 4; e++) {
            lg[e] = gred[0][e]+gred[1][e]+gred[2][e]+gred[3][e] + gb[e];
            mx = fmaxf(mx, lg[e]);
        }
        float sum = 0.f;
#pragma unroll
        for (int e = 0; e < 4; e++) { pr[e] = expf(lg[e]-mx); sum += pr[e]; }
#pragma unroll
        for (int e = 0; e < 4; e++) pr[e] /= sum;
        int i0 = 0;
#pragma unroll
        for (int e = 1; e < 4; e++) if (pr[e] > pr[i0]) i0 = e;
        int i1 = (i0 == 0) ? 1 : 0;
#pragma unroll
        for (int e = 0; e < 4; e++) if (e != i0 && pr[e] > pr[i1]) i1 = e;
        float w0 = pr[i0], w1 = pr[i1];
        float inv = 1.f / (w0 + w1);
        int pos0 = atomicAdd(&cnt[i0], 1);
        etok[i0*TT + pos0] = (int)tk;
        slot[2*tk]   = i0*TT + pos0;
        wt[2*tk]     = w0 * inv;
        int pos1 = atomicAdd(&cnt[i1], 1);
        etok[i1*TT + pos1] = (int)tk;
        slot[2*tk+1] = i1*TT + pos1;
        wt[2*tk+1]   = w1 * inv;
    }
}

// ---------------- moe combine + layernorm ----------------
__global__ void moe_combine_ln_kernel(const float* __restrict__ base, const __half* __restrict__ eo,
                                      const int* __restrict__ slot, const float* __restrict__ wt,
                                      const float* __restrict__ g, const float* __restrict__ bet,
                                      float* __restrict__ out, __half* __restrict__ out16)
{
    long t = blockIdx.x;
    int tid = threadIdx.x;
    int s0 = slot[2*t], s1 = slot[2*t+1];
    float w0 = wt[2*t], w1 = wt[2*t+1];
    float4 xh = *(const float4*)&base[t*DD + tid*4];
    uint2 e0u = *(const uint2*)&eo[(long)s0*DD + tid*4];
    uint2 e1u = *(const uint2*)&eo[(long)s1*DD + tid*4];
    float2 e0a = __half22float2(*(__half2*)&e0u.x);
    float2 e0b = __half22float2(*(__half2*)&e0u.y);
    float2 e1a = __half22float2(*(__half2*)&e1u.x);
    float2 e1b = __half22float2(*(__half2*)&e1u.y);
    float v0 = xh.x + w0*e0a.x + w1*e1a.x;
    float v1 = xh.y + w0*e0a.y + w1*e1a.y;
    float v2 = xh.z + w0*e0b.x + w1*e1b.x;
    float v3 = xh.w + w0*e0b.y + w1*e1b.y;
    float s = v0+v1+v2+v3, ss = v0*v0+v1*v1+v2*v2+v3*v3;
    __shared__ float red[16];
    int lane = tid & 31, wid = tid >> 5;
#pragma unroll
    for (int o = 16; o; o >>= 1) {
        s  += __shfl_down_sync(0xffffffffu, s, o);
        ss += __shfl_down_sync(0xffffffffu, ss, o);
    }
    if (!lane) { red[wid] = s; red[8+wid] = ss; }
    __syncthreads();
    if (!tid) {
        float S = red[0]+red[1]+red[2]+red[3];
        float Q = red[8]+red[9]+red[10]+red[11];
        red[0] = S * (1.f/DD);
        red[1] = Q * (1.f/DD);
    }
    __syncthreads();
    float m = red[0];
    float r = rsqrtf(red[1] - m*m + 1e-5f);
    float4 gv = *(const float4*)&g[tid*4];
    float4 bv = *(const float4*)&bet[tid*4];
    float4 o4;
    o4.x = (v0-m)*r*gv.x + bv.x;
    o4.y = (v1-m)*r*gv.y + bv.y;
    o4.z = (v2-m)*r*gv.z + bv.z;
    o4.w = (v3-m)*r*gv.w + bv.w;
    *(float4*)&out[t*DD + tid*4] = o4;
    __half2* hp = (__half2*)&out16[t*DD + tid*4];
    hp[0] = __floats2half2_rn(o4.x, o4.y);
    hp[1] = __floats2half2_rn(o4.z, o4.w);
}

// ======= fixed fused tail (correct version used below) =======
__global__ void __launch_bounds__(256) tail2_kernel(
    const float* __restrict__ h, const __half* __restrict__ h16,
    const __half* __restrict__ qkv,
    const __half* __restrict__ qw, const float* __restrict__ qb,
    const __half* __restrict__ ow, const float* __restrict__ obv,
    const float* __restrict__ g1, const float* __restrict__ beta1,
    const float* __restrict__ gw, const float* __restrict__ gb,
    const __half* __restrict__ ew1, const float* __restrict__ eb1,
    const __half* __restrict__ ew2, const float* __restrict__ eb2,
    const float* __restrict__ g2, const float* __restrict__ beta2,
    const float* __restrict__ hwp, const float* __restrict__ hbp,
    float* __restrict__ out)
{
    __shared__ float hr[512];
    __shared__ float q[512];
    __shared__ float sc[1024];
    __shared__ float attnv[512];
    __shared__ float ln1[512];
    __shared__ float comb[512];
    __shared__ float hid[2][1024];
    __shared__ float eo[2][512];
    __shared__ float red[16];
    __shared__ float obuf[4][64];
    __shared__ float glog[4];
    __shared__ int   eidx[2];
    __shared__ float ewt[2];

    int b = blockIdx.x;
    long tok = (long)b*SS + SS - 1;
    int tid = threadIdx.x, lane = tid & 31, warp = tid >> 5;

    for (int i = tid; i < 512; i += 256) hr[i] = h[tok*DD + i];
    const __half2* h2r = (const __half2*)(h16 + tok*DD);
    for (int oi = tid; oi < 512; oi += 256) {
        const __half2* wr = (const __half2*)(qw + (long)oi*DD);
        float acc = 0.f;
        for (int k = 0; k < 256; k++) {
            float2 hf = __half22float2(h2r[k]);
            float2 wf = __half22float2(wr[k]);
            acc += hf.x*wf.x + hf.y*wf.y;
        }
        q[oi] = acc + qb[oi];
    }
    __syncthreads();

    for (int hh = 0; hh < HH; hh++) {
        const __half* kb = qkv + (long)b*SS*(3*DD) + DD + hh*HD;
        float mymax = -1e30f;
        for (int j = tid; j < SS; j += 256) {
            const __half2* kr = (const __half2*)(kb + (long)j*(3*DD));
            float s = 0.f;
#pragma unroll
            for (int i = 0; i < 32; i++) {
                float2 kf = __half22float2(kr[i]);
                s += q[hh*64 + 2*i]*kf.x + q[hh*64 + 2*i + 1]*kf.y;
            }
            s *= 0.125f;
            sc[j] = s;
            mymax = fmaxf(mymax, s);
        }
#pragma unroll
        for (int o = 16; o; o >>= 1) mymax = fmaxf(mymax, __shfl_xor_sync(0xffffffffu, mymax, o));
        if (!lane) red[warp] = mymax;
        __syncthreads();
        float smax = fmaxf(fmaxf(fmaxf(red[0], red[1]), fmaxf(red[2], red[3])),
                           fmaxf(fmaxf(red[4], red[5]), fmaxf(red[6], red[7])));
        float mysum = 0.f;
        for (int j = tid; j < SS; j += 256) {
            float p = __expf(sc[j] - smax);
            sc[j] = p;
            mysum += p;
        }
#pragma unroll
        for (int o = 16; o; o >>= 1) mysum += __shfl_xor_sync(0xffffffffu, mysum, o);
        __syncthreads();
        if (!lane) red[warp] = mysum;
        __syncthreads();
        float ssum = red[0]+red[1]+red[2]+red[3]+red[4]+red[5]+red[6]+red[7];

        int d = tid & 63, grp = tid >> 6;
        const __half* vb = qkv + (long)b*SS*(3*DD) + 2*DD + hh*HD + d;
        float acc = 0.f;
        for (int j = grp*256; j < grp*256 + 256; j++)
            acc += sc[j] * __half2float(vb[(long)j*(3*DD)]);
        obuf[grp][d] = acc;
        __syncthreads();
        if (tid < 64)
            attnv[hh*64 + tid] = (obuf[0][tid]+obuf[1][tid]+obuf[2][tid]+obuf[3][tid]) / ssum;
        __syncthreads();
    }

    // O-proj + residual add into comb
    for (int oi = tid; oi < 512; oi += 256) {
        const __half2* wr = (const __half2*)(ow + (long)oi*DD);
        float acc = 0.f;
        for (int k = 0; k < 256; k++) {
            float2 wf = __half22float2(wr[k]);
            acc += attnv[2*k]*wf.x + attnv[2*k+1]*wf.y;
        }
        comb[oi] = hr[oi] + acc + obv[oi];
    }
    __syncthreads();

    // LN1: ln1 = LN(comb) with g1/beta1
    {
        float s = 0.f, ssq = 0.f;
        for (int i = tid; i < 512; i += 256) { float v = comb[i]; s += v; ssq += v*v; }
#pragma unroll
        for (int o = 16; o; o >>= 1) {
            s   += __shfl_xor_sync(0xffffffffu, s, o);
            ssq += __shfl_xor_sync(0xffffffffu, ssq, o);
        }
        if (!lane) { red[warp] = s; red[8+warp] = ssq; }
        __syncthreads();
        if (!tid) {
            float S = red[0]+red[1]+red[2]+red[3]+red[4]+red[5]+red[6]+red[7];
            float Q = red[8]+red[9]+red[10]+red[11]+red[12]+red[13]+red[14]+red[15];
            red[0] = S * (1.f/512.f);
            red[1] = Q * (1.f/512.f);
        }
        __syncthreads();
        float m = red[0];
        float r = rsqrtf(red[1] - m*m + 1e-5f);
        for (int i = tid; i < 512; i += 256)
            ln1[i] = (comb[i] - m) * r * g1[i] + beta1[i];
        __syncthreads();
    }

    if (warp < 4) {
        float acc = 0.f;
        for (int i = lane; i < 512; i += 32) acc += ln1[i] * gw[warp*DD + i];
#pragma unroll
        for (int o = 16; o; o >>= 1) acc += __shfl_xor_sync(0xffffffffu, acc, o);
        if (!lane) glog[warp] = acc + gb[warp];
    }
    __syncthreads();
    if (!tid) {
        float mx = fmaxf(fmaxf(glog[0], glog[1]), fmaxf(glog[2], glog[3]));
        float p[4], sum = 0.f;
#pragma unroll
        for (int e = 0; e < 4; e++) { p[e] = expf(glog[e]-mx); sum += p[e]; }
#pragma unroll
        for (int e = 0; e < 4; e++) p[e] /= sum;
        int i0 = 0;
#pragma unroll
        for (int e = 1; e < 4; e++) if (p[e] > p[i0]) i0 = e;
        int i1 = (i0 == 0) ? 1 : 0;
#pragma unroll
        for (int e = 0; e < 4; e++) if (e != i0 && p[e] > p[i1]) i1 = e;
        float inv = 1.f / (p[i0] + p[i1]);
        eidx[0] = i0; eidx[1] = i1;
        ewt[0] = p[i0]*inv; ewt[1] = p[i1]*inv;
    }
    __syncthreads();

#pragma unroll
    for (int e = 0; e < 2; e++) {
        const __half* w1 = ew1 + (long)eidx[e]*2*DD*DD;
        const float* b1 = eb1 + eidx[e]*2*DD;
        for (int f = tid; f < 1024; f += 256) {
            const __half2* wr = (const __half2*)(w1 + (long)f*DD);
            float acc = 0.f;
            for (int k = 0; k < 256; k++) {
                float2 wf = __half22float2(wr[k]);
                acc += ln1[2*k]*wf.x + ln1[2*k+1]*wf.y;
            }
            hid[e][f] = fmaxf(acc + b1[f], 0.f);
        }
    }
    __syncthreads();
#pragma unroll
    for (int e = 0; e < 2; e++) {
        const __half* w2 = ew2 + (long)eidx[e]*2*DD*DD;
        const float* b2 = eb2 + eidx[e]*DD;
        for (int d = tid; d < 512; d += 256) {
            const __half2* wr = (const __half2*)(w2 + (long)d*2*DD);
            float acc = 0.f;
            for (int k = 0; k < 512; k++) {
                float2 wf = __half22float2(wr[k]);
                acc += hid[e][2*k]*wf.x + hid[e][2*k+1]*wf.y;
            }
            eo[e][d] = acc + b2[d];
        }
    }
    __syncthreads();

    // combine + LN2 into comb
    for (int d = tid; d < 512; d += 256)
        comb[d] = ln1[d] + ewt[0]*eo[0][d] + ewt[1]*eo[1][d];
    __syncthreads();
    {
        float s = 0.f, ssq = 0.f;
        for (int i = tid; i < 512; i += 256) { float v = comb[i]; s += v; ssq += v*v; }
#pragma unroll
        for (int o = 16; o; o >>= 1) {
            s   += __shfl_xor_sync(0xffffffffu, s, o);
            ssq += __shfl_xor_sync(0xffffffffu, ssq, o);
        }
        if (!lane) { red[warp] = s; red[8+warp] = ssq; }
        __syncthreads();
        if (!tid) {
            float S = red[0]+red[1]+red[2]+red[3]+red[4]+red[5]+red[6]+red[7];
            float Q = red[8]+red[9]+red[10]+red[11]+red[12]+red[13]+red[14]+red[15];
            red[0] = S * (1.f/512.f);
            red[1] = Q * (1.f/512.f);
        }
        __syncthreads();
        float m = red[0];
        float r = rsqrtf(red[1] - m*m + 1e-5f);
        for (int i = tid; i < 512; i += 256)
            comb[i] = (comb[i] - m) * r * g2[i] + beta2[i];
        __syncthreads();
    }

    // head
    if (warp < 3) {
        float acc = 0.f;
        for (int i = lane; i < 512; i += 32) acc += comb[i] * hwp[warp*DD + i];
#pragma unroll
        for (int o = 16; o; o >>= 1) acc += __shfl_xor_sync(0xffffffffu, acc, o);
        if (!lane) out[b*3 + warp] = acc + hbp[warp];
    }
}

// ---------------- orchestration ----------------
extern "C" void kernel_launch(void* const* d_in, const int* in_sizes, int n_in,
                              void* d_out, int out_size)
{
    const float* x      = (const float*)d_in[0];
    const float* Wp     = (const float*)d_in[1];
    const float* bp     = (const float*)d_in[2];
    const float* femb   = (const float*)d_in[3];
    const float* qkv_w  = (const float*)d_in[4];
    const float* qkv_b  = (const float*)d_in[5];
    const float* ow     = (const float*)d_in[6];
    const float* ob     = (const float*)d_in[7];
    const float* g1     = (const float*)d_in[8];
    const float* beta1  = (const float*)d_in[9];
    const float* gw     = (const float*)d_in[10];
    const float* gb     = (const float*)d_in[11];
    const float* ew1    = (const float*)d_in[12];
    const float* eb1    = (const float*)d_in[13];
    const float* ew2    = (const float*)d_in[14];
    const float* eb2    = (const float*)d_in[15];
    const float* g2     = (const float*)d_in[16];
    const float* beta2  = (const float*)d_in[17];
    const float* hw     = (const float*)d_in[18];
    const float* hb     = (const float*)d_in[19];
    const int*   fidx   = (const int*)d_in[20];
    float* out = (float*)d_out;

    float *h, *wt, *istats;
    int *cnt, *etok, *slot;
    __half *h16, *qkv16, *attn16, *tmp16, *hid16, *eo16;
    __half *qkvw16, *ow16, *ew116, *ew216;
    cudaGetSymbolAddress((void**)&h,       g_h);
    cudaGetSymbolAddress((void**)&cnt,     g_cnt);
    cudaGetSymbolAddress((void**)&etok,    g_etok);
    cudaGetSymbolAddress((void**)&slot,    g_slot);
    cudaGetSymbolAddress((void**)&wt,      g_wt);
    cudaGetSymbolAddress((void**)&istats,  g_istats);
    cudaGetSymbolAddress((void**)&h16,     g_h16);
    cudaGetSymbolAddress((void**)&qkv16,   g_qkv16);
    cudaGetSymbolAddress((void**)&attn16,  g_attn16);
    cudaGetSymbolAddress((void**)&tmp16,   g_tmp16);
    cudaGetSymbolAddress((void**)&hid16,   g_hid16);
    cudaGetSymbolAddress((void**)&eo16,    g_eo16);
    cudaGetSymbolAddress((void**)&qkvw16,  g_qkvw16);
    cudaGetSymbolAddress((void**)&ow16,    g_ow16);
    cudaGetSymbolAddress((void**)&ew116,   g_ew116);
    cudaGetSymbolAddress((void**)&ew216,   g_ew216);

    cudaFuncSetAttribute(attn_h_kernel, cudaFuncAttributeMaxDynamicSharedMemorySize, ATT_SMEM);
    cudaFuncSetAttribute(gemm_h<false,false>, cudaFuncAttributeMaxDynamicSharedMemorySize, GEMM_SMEM);
    cudaFuncSetAttribute(gemm_h<true,true>,   cudaFuncAttributeMaxDynamicSharedMemorySize, GEMM_SMEM);

    f2h_all_kernel<<<(NTOTF4 + 255)/256, 256>>>(qkv_w, qkvw16, ow, ow16, ew1, ew116, ew2, ew216);

    istats_kernel<<<BB*FF, 256>>>(x, istats, cnt);
    embed_kernel<<<TT, 128>>>(x, Wp, bp, femb, fidx, istats, h, h16);

    // ---- layers 0..1: full path ----
    for (int l = 0; l < LL-1; l++) {
        gemm_h<false,false><<<dim3(3*DD/128, TT/128, 1), 256, GEMM_SMEM>>>(
            h16, qkvw16 + (long)l*3*DD*DD, qkv_b + l*3*DD, qkv16,
            TT, 3*DD, DD, DD, 3*DD, 0, 0, 0, 0, nullptr, nullptr);
        attn_h_kernel<<<dim3(SS/128, HH, BB), 256, ATT_SMEM>>>(qkv16, attn16);
        gemm_h<false,false><<<dim3(DD/128, TT/128, 1), 256, GEMM_SMEM>>>(
            attn16, ow16 + (long)l*DD*DD, ob + l*DD, tmp16,
            TT, DD, DD, DD, DD, 0, 0, 0, 0, nullptr, nullptr);
        add_ln_gate_kernel<<<TT, 128>>>(h, tmp16, g1 + l*DD, beta1 + l*DD,
                                        gw + l*EE*DD, gb + l*EE,
                                        h, h16, cnt + l*EE, etok, slot, wt);
        gemm_h<true,true><<<dim3(2*DD/128, TT/128, EE), 256, GEMM_SMEM>>>(
            h16, ew116 + (long)l*EE*2*DD*DD, eb1 + l*EE*2*DD, hid16,
            TT, 2*DD, DD, DD, 2*DD,
            0, (long)2*DD*DD, 2*DD, (long)TT*2*DD, etok, cnt + l*EE);
        gemm_h<false,false><<<dim3(DD/128, TT/128, EE), 256, GEMM_SMEM>>>(
            hid16, ew216 + (long)l*EE*2*DD*DD, eb2 + l*EE*DD, eo16,
            TT, DD, 2*DD, 2*DD, DD,
            (long)TT*2*DD, (long)2*DD*DD, DD, (long)TT*DD, nullptr, cnt + l*EE);
        moe_combine_ln_kernel<<<TT, 128>>>(h, eo16, slot, wt, g2 + l*DD, beta2 + l*DD,
                                           h, h16);
    }

    // ---- layer 2: K/V GEMM for all tokens, then fully fused single-block-per-batch tail ----
    {
        const int l = LL - 1;
        gemm_h<false,false><<<dim3(2*DD/128, TT/128, 1), 256, GEMM_SMEM>>>(
            h16, qkvw16 + (long)l*3*DD*DD + (long)DD*DD, qkv_b + l*3*DD + DD, qkv16 + DD,
            TT, 2*DD, DD, DD, 3*DD, 0, 0, 0, 0, nullptr, nullptr);
        tail2_kernel<<<BB, 256>>>(
            h, h16, qkv16,
            qkvw16 + (long)l*3*DD*DD, qkv_b + l*3*DD,
            ow16 + (long)l*DD*DD, ob + l*DD,
            g1 + l*DD, beta1 + l*DD,
            gw + l*EE*DD, gb + l*EE,
            ew116 + (long)l*EE*2*DD*DD, eb1 + l*EE*2*DD,
            ew216 + (long)l*EE*2*DD*DD, eb2 + l*EE*DD,
            g2 + l*DD, beta2 + l*DD,
            hw, hb, out);
    }
}

// round 16
// speedup vs baseline: 1.9813x; 1.9813x over previous
#include <cuda_runtime.h>
#include <cuda_fp16.h>
#include <math.h>
#include <cstdint>

#define BB 8
#define SS 1024
#define FF 8
#define DD 512
#define HH 8
#define LL 3
#define EE 4
#define TT (BB*SS)
#define HD 64

// ---------------- scratch (device globals; no allocs allowed) ----------------
__device__ float g_h[TT*DD];
__device__ int   g_cnt[LL*EE];
__device__ int   g_etok[EE*TT];
__device__ int   g_slot[2*TT];
__device__ float g_wt[2*TT];
__device__ float g_istats[BB*FF*2];
__device__ int   g_lastTok[8];

__device__ __align__(16) __half g_h16[TT*DD];
__device__ __align__(16) __half g_qkv16[TT*3*DD];
__device__ __align__(16) __half g_attn16[TT*DD];
__device__ __align__(16) __half g_tmp16[TT*DD];
__device__ __align__(16) __half g_hid16[(size_t)EE*TT*2*DD];
__device__ __align__(16) __half g_eo16[(size_t)EE*TT*DD];
__device__ __align__(16) __half g_q8[8*DD];
__device__ __align__(16) __half g_attn8[8*DD];
__device__ __align__(16) __half g_tmp8[8*DD];
__device__ __align__(16) __half g_qkvw16[LL*3*DD*DD];
__device__ __align__(16) __half g_ow16[LL*DD*DD];
__device__ __align__(16) __half g_ew116[(size_t)LL*EE*2*DD*DD];
__device__ __align__(16) __half g_ew216[(size_t)LL*EE*2*DD*DD];

__device__ __forceinline__ uint32_t smem_u32(const void* p) {
    uint32_t a;
    asm("{ .reg .u64 t; cvta.to.shared.u64 t, %1; cvt.u32.u64 %0, t; }" : "=r"(a) : "l"(p));
    return a;
}
__device__ __forceinline__ void mma_f16(float* d, const uint32_t* a, const uint32_t* b) {
    asm volatile(
      "mma.sync.aligned.m16n8k16.row.col.f32.f16.f16.f32 "
      "{%0,%1,%2,%3}, {%4,%5,%6,%7}, {%8,%9}, {%0,%1,%2,%3};"
      : "+f"(d[0]), "+f"(d[1]), "+f"(d[2]), "+f"(d[3])
      : "r"(a[0]), "r"(a[1]), "r"(a[2]), "r"(a[3]), "r"(b[0]), "r"(b[1]));
}
__device__ __forceinline__ void ldm_x4(uint32_t* r, uint32_t addr) {
    asm volatile("ldmatrix.sync.aligned.m8n8.x4.shared.b16 {%0,%1,%2,%3}, [%4];"
        : "=r"(r[0]), "=r"(r[1]), "=r"(r[2]), "=r"(r[3]) : "r"(addr));
}
__device__ __forceinline__ void ldm_x4_t(uint32_t* r, uint32_t addr) {
    asm volatile("ldmatrix.sync.aligned.m8n8.x4.trans.shared.b16 {%0,%1,%2,%3}, [%4];"
        : "=r"(r[0]), "=r"(r[1]), "=r"(r[2]), "=r"(r[3]) : "r"(addr));
}
#define CP_ASYNC16(dst, src, sz) \
  asm volatile("cp.async.cg.shared.global [%0], [%1], 16, %2;" :: "r"(dst), "l"(src), "r"(sz) : "memory")
#define CP_COMMIT() asm volatile("cp.async.commit_group;" ::: "memory")
#define CP_WAIT0()  asm volatile("cp.async.wait_group 0;" ::: "memory")
#define CP_WAIT1()  asm volatile("cp.async.wait_group 1;" ::: "memory")

__device__ __forceinline__ uint32_t h2u(__half2 h) { return *(uint32_t*)&h; }

// ---------------- merged fp32 -> fp16 weight convert ----------------
#define N1F4 (LL*3*DD*DD/4)
#define N2F4 (LL*DD*DD/4)
#define N3F4 (LL*EE*2*DD*DD/4)
#define NTOTF4 (N1F4 + N2F4 + 2*N3F4)
__global__ void f2h_all_kernel(const float* __restrict__ s1, __half* __restrict__ d1,
                               const float* __restrict__ s2, __half* __restrict__ d2,
                               const float* __restrict__ s3, __half* __restrict__ d3,
                               const float* __restrict__ s4, __half* __restrict__ d4)
{
    long i = (long)blockIdx.x * 256 + threadIdx.x;
    if (i >= NTOTF4) return;
    const float* src; __half* dst; long j;
    if (i < N1F4)                    { src = s1; dst = d1; j = i; }
    else if (i < N1F4 + N2F4)        { src = s2; dst = d2; j = i - N1F4; }
    else if (i < N1F4 + N2F4 + N3F4) { src = s3; dst = d3; j = i - N1F4 - N2F4; }
    else                             { src = s4; dst = d4; j = i - N1F4 - N2F4 - N3F4; }
    float4 v = ((const float4*)src)[j];
    __half2* op = (__half2*)(dst + 4*j);
    op[0] = __floats2half2_rn(v.x, v.y);
    op[1] = __floats2half2_rn(v.z, v.w);
}

// ========== fp16 mma GEMM (champion): 128x128 tile, 3-stage cp.async ==========
#define GBUF (128*144)
#define GEMM_SMEM (6*GBUF)
template<bool GATHER, bool RELU>
__global__ void __launch_bounds__(256) gemm_h(
    const __half* __restrict__ A, const __half* __restrict__ W,
    const float* __restrict__ bias, __half* __restrict__ C16,
    int M, int N, int Kd, int lda, int ldc,
    long astride, long wstride, int bstride, long cstride,
    const int* __restrict__ gidx, const int* __restrict__ cnts)
{
    extern __shared__ char smem[];
    int e = blockIdx.z;
    A    += (long)e * astride;
    W    += (long)e * wstride;
    bias += (long)e * bstride;
    C16  += (long)e * cstride;
    if (cnts) M = cnts[e];
    int m0 = blockIdx.y * 128;
    if (m0 >= M) return;
    int n0 = blockIdx.x * 128;

    int tid = threadIdx.x, lane = tid & 31, warp = tid >> 5;
    int g = lane >> 2, t = lane & 3;
    int wm = (warp >> 2) * 64, wn = (warp & 3) * 32;

    uint32_t sb = smem_u32(smem);
    int rbase = tid >> 3, c8 = tid & 7;

    const __half* asrc[4]; uint32_t asz[4];
    const __half* bsrc[4];
    uint32_t adst[4], bdst[4];
#pragma unroll
    for (int p = 0; p < 4; p++) {
        int row = rbase + p * 32;
        int mr = m0 + row;
        bool ok = mr < M;
        int ar = 0;
        if (ok) ar = GATHER ? gidx[(long)e * TT + mr] : mr;
        asrc[p] = A + (long)ar * lda + c8 * 8;
        asz[p] = ok ? 16u : 0u;
        bsrc[p] = W + (long)(n0 + row) * Kd + c8 * 8;
        adst[p] = sb + row * 144 + c8 * 16;
        bdst[p] = sb + 3*GBUF + row * 144 + c8 * 16;
    }

    uint32_t qrow  = (lane & 7) + ((lane >> 3) & 1) * 8;
    uint32_t khalf = (lane >> 4) * 16;
    uint32_t offA[4], offB[2];
#pragma unroll
    for (int mf = 0; mf < 4; mf++) offA[mf] = (wm + mf*16 + qrow) * 144 + khalf;
#pragma unroll
    for (int j = 0; j < 2; j++)
        offB[j] = (uint32_t)(wn + j*16 + ((lane >> 4) & 1)*8 + (lane & 7)) * 144
                + ((lane >> 3) & 1) * 16;

    float acc[4][4][4];
#pragma unroll
    for (int a_ = 0; a_ < 4; a_++)
#pragma unroll
        for (int b_ = 0; b_ < 4; b_++)
#pragma unroll
            for (int c_ = 0; c_ < 4; c_++) acc[a_][b_][c_] = 0.f;

    int nkt = Kd / 64;

    #define STAGE(s) do { \
        uint32_t _off = (uint32_t)((s) % 3) * GBUF; \
        int _ko = (s) * 64; \
        _Pragma("unroll") \
        for (int p = 0; p < 4; p++) { \
            CP_ASYNC16(adst[p] + _off, asrc[p] + _ko, asz[p]); \
            CP_ASYNC16(bdst[p] + _off, bsrc[p] + _ko, 16u); \
        } \
        CP_COMMIT(); \
    } while (0)

    STAGE(0);
    STAGE(1);

    for (int kt = 0; kt < nkt; kt++) {
        if (kt + 1 < nkt) CP_WAIT1(); else CP_WAIT0();
        __syncthreads();
        if (kt + 2 < nkt) STAGE(kt + 2);

        uint32_t ab = sb + (uint32_t)(kt % 3) * GBUF;
        uint32_t bb = sb + 3*GBUF + (uint32_t)(kt % 3) * GBUF;
#pragma unroll
        for (int ks = 0; ks < 4; ks++) {
            uint32_t af[4][4], bf[2][4];
#pragma unroll
            for (int mf = 0; mf < 4; mf++) ldm_x4(af[mf], ab + offA[mf] + ks*32);
#pragma unroll
            for (int j = 0; j < 2; j++) ldm_x4(bf[j], bb + offB[j] + ks*32);
#pragma unroll
            for (int mf = 0; mf < 4; mf++)
#pragma unroll
                for (int nf = 0; nf < 4; nf++)
                    mma_f16(acc[mf][nf], af[mf], &bf[nf >> 1][(nf & 1) * 2]);
        }
    }
    #undef STAGE

#pragma unroll
    for (int mf = 0; mf < 4; mf++) {
        int rA = m0 + wm + mf*16 + g;
        int rB = rA + 8;
#pragma unroll
        for (int nf = 0; nf < 4; nf++) {
            int col = n0 + wn + nf*8 + t*2;
            float2 bb2 = *(const float2*)&bias[col];
            float2 v0, v1;
            v0.x = acc[mf][nf][0] + bb2.x; v0.y = acc[mf][nf][1] + bb2.y;
            v1.x = acc[mf][nf][2] + bb2.x; v1.y = acc[mf][nf][3] + bb2.y;
            if (RELU) {
                v0.x = fmaxf(v0.x, 0.f); v0.y = fmaxf(v0.y, 0.f);
                v1.x = fmaxf(v1.x, 0.f); v1.y = fmaxf(v1.y, 0.f);
            }
            if (rA < M) *(__half2*)&C16[(long)rA*ldc + col] = __floats2half2_rn(v0.x, v0.y);
            if (rB < M) *(__half2*)&C16[(long)rB*ldc + col] = __floats2half2_rn(v1.x, v1.y);
        }
    }
}

// ===== attention (layers 0..1): flash fp16 mma, register-resident P =====
#define AQB 0
#define AKB 18432
#define AVB 36864
#define AKVB 9216
#define ATT_SMEM 55296
__global__ void __launch_bounds__(256) attn_h_kernel(const __half* __restrict__ qkv,
                                                     __half* __restrict__ out)
{
    extern __shared__ char smc[];
    uint32_t sb = smem_u32(smc);

    int q0 = blockIdx.x * 128;
    int hh = blockIdx.y;
    int b  = blockIdx.z;
    int tid = threadIdx.x, lane = tid & 31, warp = tid >> 5;
    int g = lane >> 2, t = lane & 3;
    const __half* base  = qkv + (long)b * SS * (3*DD) + hh * HD;
    const __half* kbase = base + DD;
    const __half* vbase = base + 2*DD;

    int srow0 = tid >> 3, sc8 = tid & 7;
    int srow1 = srow0 + 32;
    uint32_t kd0 = sb + AKB + srow0*144 + sc8*16;
    uint32_t kd1 = sb + AKB + srow1*144 + sc8*16;
    uint32_t vd0 = sb + AVB + srow0*144 + sc8*16;
    uint32_t vd1 = sb + AVB + srow1*144 + sc8*16;

    {
        const __half* k0 = kbase + (long)srow0*(3*DD) + sc8*8;
        const __half* k1 = kbase + (long)srow1*(3*DD) + sc8*8;
        const __half* v0 = vbase + (long)srow0*(3*DD) + sc8*8;
        const __half* v1 = vbase + (long)srow1*(3*DD) + sc8*8;
        CP_ASYNC16(kd0, k0, 16u); CP_ASYNC16(kd1, k1, 16u);
        CP_ASYNC16(vd0, v0, 16u); CP_ASYNC16(vd1, v1, 16u);
    }
    CP_COMMIT();

#pragma unroll
    for (int p = 0; p < 4; p++) {
        int idx = tid + p*256;
        int row = idx >> 3, c8 = idx & 7;
        *(uint4*)(smc + AQB + row*144 + c8*16) =
            *(const uint4*)(base + (long)(q0 + row) * (3*DD) + c8*8);
    }

    uint32_t qrow  = (lane & 7) + ((lane >> 3) & 1) * 8;
    uint32_t khalf = (lane >> 4) * 16;
    uint32_t offQ = sb + AQB + (warp*16 + qrow)*144 + khalf;
    uint32_t offK[4], offV[4];
#pragma unroll
    for (int j = 0; j < 4; j++)
        offK[j] = (uint32_t)(j*16 + ((lane >> 4) & 1)*8 + (lane & 7)) * 144
                + ((lane >> 3) & 1) * 16;
    {
        uint32_t kr = ((lane >> 3) & 1)*8 + (lane & 7);
#pragma unroll
        for (int j = 0; j < 4; j++)
            offV[j] = kr*144 + j*32 + ((lane >> 4) & 1)*16;
    }

    int r0 = warp*16 + g;
    float mm0 = -1e30f, mm1 = -1e30f, ll0 = 0.f, ll1 = 0.f;
    float o[8][4];
#pragma unroll
    for (int nf = 0; nf < 8; nf++)
#pragma unroll
        for (int c = 0; c < 4; c++) o[nf][c] = 0.f;

    for (int jc = 0; jc < SS/64; jc++) {
        int buf = jc & 1;
        CP_WAIT0();
        __syncthreads();
        if (jc + 1 < SS/64) {
            uint32_t nb = (uint32_t)(buf ^ 1) * AKVB;
            long goff = (long)(jc + 1) * 64 * (3*DD);
            const __half* k0 = kbase + goff + (long)srow0*(3*DD) + sc8*8;
            const __half* k1 = kbase + goff + (long)srow1*(3*DD) + sc8*8;
            const __half* v0 = vbase + goff + (long)srow0*(3*DD) + sc8*8;
            const __half* v1 = vbase + goff + (long)srow1*(3*DD) + sc8*8;
            CP_ASYNC16(kd0 + nb, k0, 16u); CP_ASYNC16(kd1 + nb, k1, 16u);
            CP_ASYNC16(vd0 + nb, v0, 16u); CP_ASYNC16(vd1 + nb, v1, 16u);
            CP_COMMIT();
        }
        uint32_t kb = sb + AKB + buf * AKVB;
        uint32_t vb = sb + AVB + buf * AKVB;

        float s[8][4];
#pragma unroll
        for (int nf = 0; nf < 8; nf++)
#pragma unroll
            for (int c = 0; c < 4; c++) s[nf][c] = 0.f;
#pragma unroll
        for (int ks = 0; ks < 4; ks++) {
            uint32_t a[4];
            ldm_x4(a, offQ + ks*32);
#pragma unroll
            for (int j = 0; j < 4; j++) {
                uint32_t bfr[4];
                ldm_x4(bfr, kb + offK[j] + ks*32);
                mma_f16(s[2*j],   a, &bfr[0]);
                mma_f16(s[2*j+1], a, &bfr[2]);
            }
        }
        float mx0 = mm0, mx1 = mm1;
#pragma unroll
        for (int nf = 0; nf < 8; nf++) {
            s[nf][0] *= 0.125f; s[nf][1] *= 0.125f;
            s[nf][2] *= 0.125f; s[nf][3] *= 0.125f;
            mx0 = fmaxf(mx0, fmaxf(s[nf][0], s[nf][1]));
            mx1 = fmaxf(mx1, fmaxf(s[nf][2], s[nf][3]));
        }
        mx0 = fmaxf(mx0, __shfl_xor_sync(0xffffffffu, mx0, 1));
        mx0 = fmaxf(mx0, __shfl_xor_sync(0xffffffffu, mx0, 2));
        mx1 = fmaxf(mx1, __shfl_xor_sync(0xffffffffu, mx1, 1));
        mx1 = fmaxf(mx1, __shfl_xor_sync(0xffffffffu, mx1, 2));
        float al0 = __expf(mm0 - mx0), al1 = __expf(mm1 - mx1);
        float sum0 = 0.f, sum1 = 0.f;
#pragma unroll
        for (int nf = 0; nf < 8; nf++) {
            s[nf][0] = __expf(s[nf][0] - mx0);
            s[nf][1] = __expf(s[nf][1] - mx0);
            s[nf][2] = __expf(s[nf][2] - mx1);
            s[nf][3] = __expf(s[nf][3] - mx1);
            sum0 += s[nf][0] + s[nf][1];
            sum1 += s[nf][2] + s[nf][3];
        }
        sum0 += __shfl_xor_sync(0xffffffffu, sum0, 1);
        sum0 += __shfl_xor_sync(0xffffffffu, sum0, 2);
        sum1 += __shfl_xor_sync(0xffffffffu, sum1, 1);
        sum1 += __shfl_xor_sync(0xffffffffu, sum1, 2);
        ll0 = ll0*al0 + sum0; ll1 = ll1*al1 + sum1;
        mm0 = mx0; mm1 = mx1;
#pragma unroll
        for (int nf = 0; nf < 8; nf++) {
            o[nf][0] *= al0; o[nf][1] *= al0;
            o[nf][2] *= al1; o[nf][3] *= al1;
        }
#pragma unroll
        for (int ks = 0; ks < 4; ks++) {
            uint32_t a[4];
            a[0] = h2u(__floats2half2_rn(s[2*ks][0],   s[2*ks][1]));
            a[1] = h2u(__floats2half2_rn(s[2*ks][2],   s[2*ks][3]));
            a[2] = h2u(__floats2half2_rn(s[2*ks+1][0], s[2*ks+1][1]));
            a[3] = h2u(__floats2half2_rn(s[2*ks+1][2], s[2*ks+1][3]));
#pragma unroll
            for (int j = 0; j < 4; j++) {
                uint32_t bfr[4];
                ldm_x4_t(bfr, vb + offV[j] + ks*2304);
                mma_f16(o[2*j],   a, &bfr[0]);
                mma_f16(o[2*j+1], a, &bfr[2]);
            }
        }
    }

    float inv0 = 1.f / ll0, inv1 = 1.f / ll1;
    long tok0 = (long)(b*SS + q0 + r0) * DD + hh*HD;
    long tok1 = tok0 + 8L*DD;
#pragma unroll
    for (int nf = 0; nf < 8; nf++) {
        int col = nf*8 + 2*t;
        *(__half2*)&out[tok0 + col] = __floats2half2_rn(o[nf][0]*inv0, o[nf][1]*inv0);
        *(__half2*)&out[tok1 + col] = __floats2half2_rn(o[nf][2]*inv1, o[nf][3]*inv1);
    }
}

// ======= last-layer attention: 1 query (last token) per (h,b), fp32 =======
__global__ void __launch_bounds__(256) attn_last_kernel(const __half* __restrict__ qkv,
                                                        const __half* __restrict__ q8,
                                                        __half* __restrict__ attn8)
{
    __shared__ float qs[64];
    __shared__ float sc[1024];
    __shared__ float red[8];
    __shared__ float obuf[4][64];
    int hh = blockIdx.x, b = blockIdx.y;
    int tid = threadIdx.x, lane = tid & 31, warp = tid >> 5;

    if (tid < 64) qs[tid] = __half2float(q8[b*DD + hh*HD + tid]) * 0.125f;
    __syncthreads();

    const __half* kb = qkv + (long)b * SS * (3*DD) + DD + hh * HD;
    float mymax = -1e30f;
    for (int j = tid; j < SS; j += 256) {
        const __half2* kr = (const __half2*)(kb + (long)j * (3*DD));
        float s = 0.f;
#pragma unroll
        for (int i = 0; i < 32; i++) {
            float2 kf = __half22float2(kr[i]);
            s += qs[2*i] * kf.x + qs[2*i+1] * kf.y;
        }
        sc[j] = s;
        mymax = fmaxf(mymax, s);
    }
#pragma unroll
    for (int o = 16; o; o >>= 1) mymax = fmaxf(mymax, __shfl_xor_sync(0xffffffffu, mymax, o));
    if (!lane) red[warp] = mymax;
    __syncthreads();
    float smax = fmaxf(fmaxf(fmaxf(red[0], red[1]), fmaxf(red[2], red[3])),
                       fmaxf(fmaxf(red[4], red[5]), fmaxf(red[6], red[7])));
    float mysum = 0.f;
    for (int j = tid; j < SS; j += 256) {
        float p = __expf(sc[j] - smax);
        sc[j] = p;
        mysum += p;
    }
#pragma unroll
    for (int o = 16; o; o >>= 1) mysum += __shfl_xor_sync(0xffffffffu, mysum, o);
    __syncthreads();
    if (!lane) red[warp] = mysum;
    __syncthreads();
    float ssum = red[0]+red[1]+red[2]+red[3]+red[4]+red[5]+red[6]+red[7];

    int d = tid & 63, grp = tid >> 6;
    const __half* vb = qkv + (long)b * SS * (3*DD) + 2*DD + hh * HD + d;
    float acc = 0.f;
    for (int j = grp*256; j < grp*256 + 256; j++)
        acc += sc[j] * __half2float(vb[(long)j * (3*DD)]);
    obuf[grp][d] = acc;
    __syncthreads();
    if (tid < 64) {
        float o = (obuf[0][tid] + obuf[1][tid] + obuf[2][tid] + obuf[3][tid]) / ssum;
        attn8[b*DD + hh*HD + tid] = __float2half(o);
    }
}

// ---------------- instance-norm stats (+ zero MoE counters, fill lastTok) ----------------
__global__ void istats_kernel(const float* __restrict__ x, float* __restrict__ stats,
                              int* __restrict__ cntAll, int* __restrict__ lastTok)
{
    int bf = blockIdx.x;
    int b = bf >> 3, f = bf & 7;
    int tid = threadIdx.x;
    if (bf == 0 && tid < LL*EE) cntAll[tid] = 0;
    if (bf == 0 && tid < 8) lastTok[tid] = tid*SS + SS - 1;
    float s = 0.f, ss = 0.f;
    for (int i = tid; i < SS; i += 256) {
        float v = x[((long)b*SS + i)*FF + f];
        s += v; ss += v*v;
    }
    __shared__ float red[16];
    int lane = tid & 31, wid = tid >> 5;
#pragma unroll
    for (int o = 16; o; o >>= 1) {
        s  += __shfl_down_sync(0xffffffffu, s, o);
        ss += __shfl_down_sync(0xffffffffu, ss, o);
    }
    if (!lane) { red[wid] = s; red[8+wid] = ss; }
    __syncthreads();
    if (!tid) {
        float S = 0.f, Q = 0.f;
        for (int w = 0; w < 8; w++) { S += red[w]; Q += red[8+w]; }
        float m = S / SS;
        float var = (Q - SS*m*m) / (SS - 1);
        stats[bf*2]   = m;
        stats[bf*2+1] = 1.f / (sqrtf(var) + 1e-5f);
    }
}

// ---------------- embed (fp32 residual + fp16 shadow) ----------------
__global__ void embed_kernel(const float* __restrict__ x, const float* __restrict__ Wp,
                             const float* __restrict__ bp, const float* __restrict__ femb,
                             const int* __restrict__ fidx, const float* __restrict__ stats,
                             float* __restrict__ h, __half* __restrict__ h16)
{
    int token = blockIdx.x;
    int b = token >> 10, s = token & 1023;
    int tid = threadIdx.x;
    __shared__ float xn[8];
    if (tid < 8) {
        float m = stats[(b*8+tid)*2], inv = stats[(b*8+tid)*2+1];
        xn[tid] = (x[(long)token*FF + tid] - m) * inv;
    }
    __syncthreads();
    int fi = *fidx;
    int d0 = tid * 4;
    float4 acc = *(const float4*)&bp[d0];
    float* ap = &acc.x;
#pragma unroll
    for (int f = 0; f < 8; f++) {
        float xv = xn[f];
        ap[0] += xv * Wp[(d0+0)*8+f];
        ap[1] += xv * Wp[(d0+1)*8+f];
        ap[2] += xv * Wp[(d0+2)*8+f];
        ap[3] += xv * Wp[(d0+3)*8+f];
    }
    const float c = -0.0179889460f;
#pragma unroll
    for (int j = 0; j < 4; j++) {
        int d = d0 + j;
        int i = d >> 1;
        float ang = (float)s * expf((float)(2*i) * c);
        float pe = (d & 1) ? cosf(ang) : sinf(ang);
        ap[j] += femb[fi*DD + d] + pe;
    }
    *(float4*)&h[(long)token*DD + d0] = acc;
    __half2* hp = (__half2*)&h16[(long)token*DD + d0];
    hp[0] = __floats2half2_rn(acc.x, acc.y);
    hp[1] = __floats2half2_rn(acc.z, acc.w);
}

// ---------------- add + layernorm + fused gating (fp32 base; optional tokmap) ----------------
__global__ void add_ln_gate_kernel(const float* __restrict__ base, const __half* __restrict__ add,
                                   const float* __restrict__ g, const float* __restrict__ bet,
                                   const float* __restrict__ gw, const float* __restrict__ gb,
                                   float* __restrict__ out, __half* __restrict__ out16,
                                   int* __restrict__ cnt, int* __restrict__ etok,
                                   int* __restrict__ slot, float* __restrict__ wt,
                                   const int* __restrict__ tokmap)
{
    long bx = blockIdx.x;
    long tk = tokmap ? (long)tokmap[bx] : bx;
    long addRow = tokmap ? bx : tk;
    int tid = threadIdx.x;
    float4 xb = *(const float4*)&base[tk*DD + tid*4];
    uint2 au = *(const uint2*)&add[addRow*DD + tid*4];
    float2 aa = __half22float2(*(__half2*)&au.x);
    float2 ab = __half22float2(*(__half2*)&au.y);
    float v0=xb.x+aa.x, v1=xb.y+aa.y, v2=xb.z+ab.x, v3=xb.w+ab.y;
    float s = v0+v1+v2+v3, ss = v0*v0+v1*v1+v2*v2+v3*v3;
    __shared__ float red[16];
    __shared__ float gred[4][4];
    int lane = tid & 31, wid = tid >> 5;
#pragma unroll
    for (int o = 16; o; o >>= 1) {
        s  += __shfl_down_sync(0xffffffffu, s, o);
        ss += __shfl_down_sync(0xffffffffu, ss, o);
    }
    if (!lane) { red[wid] = s; red[8+wid] = ss; }
    __syncthreads();
    if (!tid) {
        float S = red[0]+red[1]+red[2]+red[3];
        float Q = red[8]+red[9]+red[10]+red[11];
        red[0] = S * (1.f/DD);
        red[1] = Q * (1.f/DD);
    }
    __syncthreads();
    float m = red[0];
    float r = rsqrtf(red[1] - m*m + 1e-5f);
    float4 gv = *(const float4*)&g[tid*4];
    float4 bv = *(const float4*)&bet[tid*4];
    float4 o4;
    o4.x = (v0-m)*r*gv.x + bv.x;
    o4.y = (v1-m)*r*gv.y + bv.y;
    o4.z = (v2-m)*r*gv.z + bv.z;
    o4.w = (v3-m)*r*gv.w + bv.w;
    *(float4*)&out[tk*DD + tid*4] = o4;
    __half2* hp = (__half2*)&out16[tk*DD + tid*4];
    hp[0] = __floats2half2_rn(o4.x, o4.y);
    hp[1] = __floats2half2_rn(o4.z, o4.w);

    float p[4];
#pragma unroll
    for (int e = 0; e < 4; e++) {
        float4 wv = *(const float4*)&gw[e*DD + tid*4];
        p[e] = o4.x*wv.x + o4.y*wv.y + o4.z*wv.z + o4.w*wv.w;
    }
#pragma unroll
    for (int e = 0; e < 4; e++)
#pragma unroll
        for (int o = 16; o; o >>= 1)
            p[e] += __shfl_down_sync(0xffffffffu, p[e], o);
    if (!lane) {
        gred[wid][0] = p[0]; gred[wid][1] = p[1];
        gred[wid][2] = p[2]; gred[wid][3] = p[3];
    }
    __syncthreads();
    if (!tid) {
        float lg[4], pr[4];
        float mx = -1e30f;
#pragma unroll
        for (int e = 0; e < 4; e++) {
            lg[e] = gred[0][e]+gred[1][e]+gred[2][e]+gred[3][e] + gb[e];
            mx = fmaxf(mx, lg[e]);
        }
        float sum = 0.f;
#pragma unroll
        for (int e = 0; e < 4; e++) { pr[e] = expf(lg[e]-mx); sum += pr[e]; }
#pragma unroll
        for (int e = 0; e < 4; e++) pr[e] /= sum;
        int i0 = 0;
#pragma unroll
        for (int e = 1; e < 4; e++) if (pr[e] > pr[i0]) i0 = e;
        int i1 = (i0 == 0) ? 1 : 0;
#pragma unroll
        for (int e = 0; e < 4; e++) if (e != i0 && pr[e] > pr[i1]) i1 = e;
        float w0 = pr[i0], w1 = pr[i1];
        float inv = 1.f / (w0 + w1);
        int pos0 = atomicAdd(&cnt[i0], 1);
        etok[i0*TT + pos0] = (int)tk;
        slot[2*tk]   = i0*TT + pos0;
        wt[2*tk]     = w0 * inv;
        int pos1 = atomicAdd(&cnt[i1], 1);
        etok[i1*TT + pos1] = (int)tk;
        slot[2*tk+1] = i1*TT + pos1;
        wt[2*tk+1]   = w1 * inv;
    }
}

// ---------------- moe combine + layernorm (fp32 base; optional tokmap) ----------------
__global__ void moe_combine_ln_kernel(const float* __restrict__ base, const __half* __restrict__ eo,
                                      const int* __restrict__ slot, const float* __restrict__ wt,
                                      const float* __restrict__ g, const float* __restrict__ bet,
                                      float* __restrict__ out, __half* __restrict__ out16,
                                      const int* __restrict__ tokmap)
{
    long bx = blockIdx.x;
    long t = tokmap ? (long)tokmap[bx] : bx;
    int tid = threadIdx.x;
    int s0 = slot[2*t], s1 = slot[2*t+1];
    float w0 = wt[2*t], w1 = wt[2*t+1];
    float4 xh = *(const float4*)&base[t*DD + tid*4];
    uint2 e0u = *(const uint2*)&eo[(long)s0*DD + tid*4];
    uint2 e1u = *(const uint2*)&eo[(long)s1*DD + tid*4];
    float2 e0a = __half22float2(*(__half2*)&e0u.x);
    float2 e0b = __half22float2(*(__half2*)&e0u.y);
    float2 e1a = __half22float2(*(__half2*)&e1u.x);
    float2 e1b = __half22float2(*(__half2*)&e1u.y);
    float v0 = xh.x + w0*e0a.x + w1*e1a.x;
    float v1 = xh.y + w0*e0a.y + w1*e1a.y;
    float v2 = xh.z + w0*e0b.x + w1*e1b.x;
    float v3 = xh.w + w0*e0b.y + w1*e1b.y;
    float s = v0+v1+v2+v3, ss = v0*v0+v1*v1+v2*v2+v3*v3;
    __shared__ float red[16];
    int lane = tid & 31, wid = tid >> 5;
#pragma unroll
    for (int o = 16; o; o >>= 1) {
        s  += __shfl_down_sync(0xffffffffu, s, o);
        ss += __shfl_down_sync(0xffffffffu, ss, o);
    }
    if (!lane) { red[wid] = s; red[8+wid] = ss; }
    __syncthreads();
    if (!tid) {
        float S = red[0]+red[1]+red[2]+red[3];
        float Q = red[8]+red[9]+red[10]+red[11];
        red[0] = S * (1.f/DD);
        red[1] = Q * (1.f/DD);
    }
    __syncthreads();
    float m = red[0];
    float r = rsqrtf(red[1] - m*m + 1e-5f);
    float4 gv = *(const float4*)&g[tid*4];
    float4 bv = *(const float4*)&bet[tid*4];
    float4 o4;
    o4.x = (v0-m)*r*gv.x + bv.x;
    o4.y = (v1-m)*r*gv.y + bv.y;
    o4.z = (v2-m)*r*gv.z + bv.z;
    o4.w = (v3-m)*r*gv.w + bv.w;
    *(float4*)&out[t*DD + tid*4] = o4;
    __half2* hp = (__half2*)&out16[t*DD + tid*4];
    hp[0] = __floats2half2_rn(o4.x, o4.y);
    hp[1] = __floats2half2_rn(o4.z, o4.w);
}

// ---------------- head (fp32 residual) ----------------
__global__ void head_kernel(const float* __restrict__ h, const float* __restrict__ hw,
                            const float* __restrict__ hb, float* __restrict__ out)
{
    int w = threadIdx.x >> 5, lane = threadIdx.x & 31;
    int b = w / 3, i = w % 3;
    const float* hp = h + ((long)(b*SS + SS-1)) * DD;
    float s = 0.f;
#pragma unroll
    for (int it = 0; it < 4; it++) {
        int d0 = (it*32 + lane) * 4;
        float4 a = *(const float4*)&hp[d0];
        float4 c = *(const float4*)&hw[i*DD + d0];
        s += a.x*c.x + a.y*c.y + a.z*c.z + a.w*c.w;
    }
#pragma unroll
    for (int o = 16; o; o >>= 1) s += __shfl_down_sync(0xffffffffu, s, o);
    if (!lane) out[b*3+i] = s + hb[i];
}

// ---------------- orchestration ----------------
extern "C" void kernel_launch(void* const* d_in, const int* in_sizes, int n_in,
                              void* d_out, int out_size)
{
    const float* x      = (const float*)d_in[0];
    const float* Wp     = (const float*)d_in[1];
    const float* bp     = (const float*)d_in[2];
    const float* femb   = (const float*)d_in[3];
    const float* qkv_w  = (const float*)d_in[4];
    const float* qkv_b  = (const float*)d_in[5];
    const float* ow     = (const float*)d_in[6];
    const float* ob     = (const float*)d_in[7];
    const float* g1     = (const float*)d_in[8];
    const float* beta1  = (const float*)d_in[9];
    const float* gw     = (const float*)d_in[10];
    const float* gb     = (const float*)d_in[11];
    const float* ew1    = (const float*)d_in[12];
    const float* eb1    = (const float*)d_in[13];
    const float* ew2    = (const float*)d_in[14];
    const float* eb2    = (const float*)d_in[15];
    const float* g2     = (const float*)d_in[16];
    const float* beta2  = (const float*)d_in[17];
    const float* hw     = (const float*)d_in[18];
    const float* hb     = (const float*)d_in[19];
    const int*   fidx   = (const int*)d_in[20];
    float* out = (float*)d_out;

    float *h, *wt, *istats;
    int *cnt, *etok, *slot, *lastTok;
    __half *h16, *qkv16, *attn16, *tmp16, *hid16, *eo16, *q8, *attn8, *tmp8;
    __half *qkvw16, *ow16, *ew116, *ew216;
    cudaGetSymbolAddress((void**)&h,       g_h);
    cudaGetSymbolAddress((void**)&cnt,     g_cnt);
    cudaGetSymbolAddress((void**)&etok,    g_etok);
    cudaGetSymbolAddress((void**)&slot,    g_slot);
    cudaGetSymbolAddress((void**)&wt,      g_wt);
    cudaGetSymbolAddress((void**)&istats,  g_istats);
    cudaGetSymbolAddress((void**)&lastTok, g_lastTok);
    cudaGetSymbolAddress((void**)&h16,     g_h16);
    cudaGetSymbolAddress((void**)&qkv16,   g_qkv16);
    cudaGetSymbolAddress((void**)&attn16,  g_attn16);
    cudaGetSymbolAddress((void**)&tmp16,   g_tmp16);
    cudaGetSymbolAddress((void**)&hid16,   g_hid16);
    cudaGetSymbolAddress((void**)&eo16,    g_eo16);
    cudaGetSymbolAddress((void**)&q8,      g_q8);
    cudaGetSymbolAddress((void**)&attn8,   g_attn8);
    cudaGetSymbolAddress((void**)&tmp8,    g_tmp8);
    cudaGetSymbolAddress((void**)&qkvw16,  g_qkvw16);
    cudaGetSymbolAddress((void**)&ow16,    g_ow16);
    cudaGetSymbolAddress((void**)&ew116,   g_ew116);
    cudaGetSymbolAddress((void**)&ew216,   g_ew216);

    cudaFuncSetAttribute(attn_h_kernel, cudaFuncAttributeMaxDynamicSharedMemorySize, ATT_SMEM);
    cudaFuncSetAttribute(gemm_h<false,false>, cudaFuncAttributeMaxDynamicSharedMemorySize, GEMM_SMEM);
    cudaFuncSetAttribute(gemm_h<true,false>,  cudaFuncAttributeMaxDynamicSharedMemorySize, GEMM_SMEM);
    cudaFuncSetAttribute(gemm_h<true,true>,   cudaFuncAttributeMaxDynamicSharedMemorySize, GEMM_SMEM);

    f2h_all_kernel<<<(NTOTF4 + 255)/256, 256>>>(qkv_w, qkvw16, ow, ow16, ew1, ew116, ew2, ew216);

    istats_kernel<<<BB*FF, 256>>>(x, istats, cnt, lastTok);
    embed_kernel<<<TT, 128>>>(x, Wp, bp, femb, fidx, istats, h, h16);

    // ---- layers 0..1: full path ----
    for (int l = 0; l < LL-1; l++) {
        gemm_h<false,false><<<dim3(3*DD/128, TT/128, 1), 256, GEMM_SMEM>>>(
            h16, qkvw16 + (long)l*3*DD*DD, qkv_b + l*3*DD, qkv16,
            TT, 3*DD, DD, DD, 3*DD, 0, 0, 0, 0, nullptr, nullptr);
        attn_h_kernel<<<dim3(SS/128, HH, BB), 256, ATT_SMEM>>>(qkv16, attn16);
        gemm_h<false,false><<<dim3(DD/128, TT/128, 1), 256, GEMM_SMEM>>>(
            attn16, ow16 + (long)l*DD*DD, ob + l*DD, tmp16,
            TT, DD, DD, DD, DD, 0, 0, 0, 0, nullptr, nullptr);
        add_ln_gate_kernel<<<TT, 128>>>(h, tmp16, g1 + l*DD, beta1 + l*DD,
                                        gw + l*EE*DD, gb + l*EE,
                                        h, h16, cnt + l*EE, etok, slot, wt, nullptr);
        gemm_h<true,true><<<dim3(2*DD/128, TT/128, EE), 256, GEMM_SMEM>>>(
            h16, ew116 + (long)l*EE*2*DD*DD, eb1 + l*EE*2*DD, hid16,
            TT, 2*DD, DD, DD, 2*DD,
            0, (long)2*DD*DD, 2*DD, (long)TT*2*DD, etok, cnt + l*EE);
        gemm_h<false,false><<<dim3(DD/128, TT/128, EE), 256, GEMM_SMEM>>>(
            hid16, ew216 + (long)l*EE*2*DD*DD, eb2 + l*EE*DD, eo16,
            TT, DD, 2*DD, 2*DD, DD,
            (long)TT*2*DD, (long)2*DD*DD, DD, (long)TT*DD, nullptr, cnt + l*EE);
        moe_combine_ln_kernel<<<TT, 128>>>(h, eo16, slot, wt, g2 + l*DD, beta2 + l*DD,
                                           h, h16, nullptr);
    }

    // ---- layer 2: only last token of each batch matters downstream ----
    {
        const int l = LL - 1;
        gemm_h<false,false><<<dim3(2*DD/128, TT/128, 1), 256, GEMM_SMEM>>>(
            h16, qkvw16 + (long)l*3*DD*DD + (long)DD*DD, qkv_b + l*3*DD + DD, qkv16 + DD,
            TT, 2*DD, DD, DD, 3*DD, 0, 0, 0, 0, nullptr, nullptr);
        gemm_h<true,false><<<dim3(DD/128, 1, 1), 256, GEMM_SMEM>>>(
            h16, qkvw16 + (long)l*3*DD*DD, qkv_b + l*3*DD, q8,
            8, DD, DD, DD, DD, 0, 0, 0, 0, lastTok, nullptr);
        attn_last_kernel<<<dim3(HH, BB), 256>>>(qkv16, q8, attn8);
        gemm_h<false,false><<<dim3(DD/128, 1, 1), 256, GEMM_SMEM>>>(
            attn8, ow16 + (long)l*DD*DD, ob + l*DD, tmp8,
            8, DD, DD, DD, DD, 0, 0, 0, 0, nullptr, nullptr);
        add_ln_gate_kernel<<<8, 128>>>(h, tmp8, g1 + l*DD, beta1 + l*DD,
                                       gw + l*EE*DD, gb + l*EE,
                                       h, h16, cnt + l*EE, etok, slot, wt, lastTok);
        gemm_h<true,true><<<dim3(2*DD/128, 1, EE), 256, GEMM_SMEM>>>(
            h16, ew116 + (long)l*EE*2*DD*DD, eb1 + l*EE*2*DD, hid16,
            TT, 2*DD, DD, DD, 2*DD,
            0, (long)2*DD*DD, 2*DD, (long)TT*2*DD, etok, cnt + l*EE);
        gemm_h<false,false><<<dim3(DD/128, 1, EE), 256, GEMM_SMEM>>>(
            hid16, ew216 + (long)l*EE*2*DD*DD, eb2 + l*EE*DD, eo16,
            TT, DD, 2*DD, 2*DD, DD,
            (long)TT*2*DD, (long)2*DD*DD, DD, (long)TT*DD, nullptr, cnt + l*EE);
        moe_combine_ln_kernel<<<8, 128>>>(h, eo16, slot, wt, g2 + l*DD, beta2 + l*DD,
                                          h, h16, lastTok);
    }
    head_kernel<<<1, 768>>>(h, hw, hb, out);
}